// round 1
// baseline (speedup 1.0000x reference)
#include <cuda_runtime.h>
#include <math.h>

// Shapes (fixed by the problem)
#define B 32
#define C 256
#define H 64
#define W 64
#define HW (H*W)            // 4096
#define PLANES (B*C)        // 8192
#define RH 3                // int(0.05*64)
#define RW 6                // int(0.1*64)
#define CLAMP_SX 61.0f      // h - rh
#define CLAMP_SY 58.0f      // w - rw

// Scratch (no cudaMalloc allowed)
__device__ float g_mean[PLANES];
__device__ float g_scale[PLANES];
__device__ int   g_sx[PLANES];
__device__ int   g_sy[PLANES];

// ---------------------------------------------------------------------------
// Kernel 1: per-(b,c) mean of x over the 4096-element plane.
// One block per plane, 256 threads, float4 loads (fully coalesced).
// ---------------------------------------------------------------------------
__global__ void k_mean(const float* __restrict__ x) {
    int plane = blockIdx.x;
    const float4* xp = reinterpret_cast<const float4*>(x) + (size_t)plane * (HW / 4);
    int tid = threadIdx.x;

    float s = 0.f;
#pragma unroll
    for (int i = 0; i < 4; i++) {
        float4 v = xp[tid + i * 256];
        s += (v.x + v.y) + (v.z + v.w);
    }
#pragma unroll
    for (int o = 16; o; o >>= 1) s += __shfl_xor_sync(0xffffffffu, s, o);

    __shared__ float ws[8];
    if ((tid & 31) == 0) ws[tid >> 5] = s;
    __syncthreads();
    if (tid == 0) {
        float t = 0.f;
#pragma unroll
        for (int i = 0; i < 8; i++) t += ws[i];
        g_mean[plane] = t * (1.0f / (float)HW);
    }
}

// ---------------------------------------------------------------------------
// Kernel 2: all the tiny MLP math. One block per batch element, 256 threads.
//   scale = sigmoid(relu(y @ se_w1^T) @ se_w2^T)           (SE gate)
//   g     = y * scale                                      (mean of x_se)
//   sx    = min(ceil(64*sigmoid(dyrelu(g@ch_w^T+ch_b))),61)
//   sy    = min(ceil(64*sigmoid(dyrelu(g@cw_w^T+cw_b))),58)
// ---------------------------------------------------------------------------
__device__ __forceinline__ float sigmoidf_acc(float v) {
    return 1.0f / (1.0f + expf(-v));
}

__device__ void dyrelu_branch(
    int b, int tid,
    const float* __restrict__ gv,      // smem[256]: gated means
    const float* __restrict__ cw,      // (256,256)
    const float* __restrict__ cb,      // (256,)
    const float* __restrict__ fc1w,    // (64,256)
    const float* __restrict__ fc1b,    // (64,)
    const float* __restrict__ fc2w,    // (1024,64)
    const float* __restrict__ fc2b,    // (1024,)
    float clampv,
    int* __restrict__ outArr,
    float* vh, float* th1)             // smem scratch [256], [64]
{
    // vh[c] = g . cw[c,:] + cb[c]
    {
        float acc = cb[tid];
        const float* wr = cw + tid * 256;
#pragma unroll 8
        for (int c = 0; c < 256; c++) acc = fmaf(gv[c], wr[c], acc);
        vh[tid] = acc;
    }
    __syncthreads();

    // th1[j] = relu(vh . fc1w[j,:] + fc1b[j]),  j < 64
    if (tid < 64) {
        float s = fc1b[tid];
        const float* r = fc1w + tid * 256;
#pragma unroll 8
        for (int c = 0; c < 256; c++) s = fmaf(vh[c], r[c], s);
        th1[tid] = fmaxf(s, 0.f);
    }
    __syncthreads();

    // per-channel coefficients (4 outputs of fc2 per channel)
    float v = vh[tid];
    float th[4];
#pragma unroll
    for (int k = 0; k < 4; k++) {
        int m = tid * 4 + k;
        float s = fc2b[m];
        const float* r = fc2w + m * 64;
#pragma unroll 8
        for (int j = 0; j < 64; j++) s = fmaf(th1[j], r[j], s);
        th[k] = 2.0f * sigmoidf_acc(s) - 1.0f;
    }
    // LAMBDAS=[1,1,.5,.5], INIT_V=[1,0,0,0]
    float a0 = th[0] + 1.0f;
    float a1 = th[1];
    float b0 = 0.5f * th[2];
    float b1 = 0.5f * th[3];
    float dy = fmaxf(fmaf(v, a0, b0), fmaf(v, a1, b1));
    float sg = sigmoidf_acc(dy);
    float sx = fminf(ceilf(64.0f * sg), clampv);
    outArr[b * 256 + tid] = (int)sx;
    __syncthreads();   // before smem reuse by the second branch
}

__global__ void k_mlp(
    const float* __restrict__ se_w1,   // (16,256)
    const float* __restrict__ se_w2,   // (256,16)
    const float* __restrict__ ch_w, const float* __restrict__ ch_b,
    const float* __restrict__ cw_w, const float* __restrict__ cw_b,
    const float* __restrict__ dh_fc1w, const float* __restrict__ dh_fc1b,
    const float* __restrict__ dh_fc2w, const float* __restrict__ dh_fc2b,
    const float* __restrict__ dw_fc1w, const float* __restrict__ dw_fc1b,
    const float* __restrict__ dw_fc2w, const float* __restrict__ dw_fc2b)
{
    __shared__ float y[256];
    __shared__ float t1[16];
    __shared__ float gv[256];
    __shared__ float vh[256];
    __shared__ float th1[64];

    int b = blockIdx.x;
    int tid = threadIdx.x;

    y[tid] = g_mean[b * 256 + tid];
    __syncthreads();

    // SE squeeze: t1 = relu(y @ se_w1^T)
    if (tid < 16) {
        float s = 0.f;
        const float* r = se_w1 + tid * 256;
#pragma unroll 8
        for (int c = 0; c < 256; c++) s = fmaf(y[c], r[c], s);
        t1[tid] = fmaxf(s, 0.f);
    }
    __syncthreads();

    // SE excite: scale = sigmoid(t1 @ se_w2^T); g = y * scale
    {
        float s = 0.f;
        const float* r = se_w2 + tid * 16;
#pragma unroll
        for (int j = 0; j < 16; j++) s = fmaf(t1[j], r[j], s);
        float sg = sigmoidf_acc(s);
        g_scale[b * 256 + tid] = sg;
        gv[tid] = y[tid] * sg;
    }
    __syncthreads();

    dyrelu_branch(b, tid, gv, ch_w, ch_b, dh_fc1w, dh_fc1b, dh_fc2w, dh_fc2b,
                  CLAMP_SX, g_sx, vh, th1);
    dyrelu_branch(b, tid, gv, cw_w, cw_b, dw_fc1w, dw_fc1b, dw_fc2w, dw_fc2b,
                  CLAMP_SY, g_sy, vh, th1);
}

// ---------------------------------------------------------------------------
// Kernel 3: out = x * scale * !inside. One block per plane, float4 I/O.
// Each float4 covers 4 consecutive cols within one row (W=64, aligned).
// ---------------------------------------------------------------------------
__global__ void k_apply(const float* __restrict__ x, float* __restrict__ out) {
    int plane = blockIdx.x;
    float sc = g_scale[plane];
    int sx = g_sx[plane];
    int sy = g_sy[plane];

    const float4* xp = reinterpret_cast<const float4*>(x) + (size_t)plane * (HW / 4);
    float4* op = reinterpret_cast<float4*>(out) + (size_t)plane * (HW / 4);
    int tid = threadIdx.x;

#pragma unroll
    for (int i = 0; i < 4; i++) {
        int p = tid + i * 256;       // float4 index within plane
        int e = p * 4;               // element index
        int row = e >> 6;            // / 64
        int col = e & 63;            // % 64
        float4 v = xp[p];
        v.x *= sc; v.y *= sc; v.z *= sc; v.w *= sc;
        if (row >= sx && row < sx + RH) {
            if (col + 0 >= sy && col + 0 < sy + RW) v.x = 0.f;
            if (col + 1 >= sy && col + 1 < sy + RW) v.y = 0.f;
            if (col + 2 >= sy && col + 2 < sy + RW) v.z = 0.f;
            if (col + 3 >= sy && col + 3 < sy + RW) v.w = 0.f;
        }
        op[p] = v;
    }
}

// ---------------------------------------------------------------------------
extern "C" void kernel_launch(void* const* d_in, const int* in_sizes, int n_in,
                              void* d_out, int out_size) {
    const float* x       = (const float*)d_in[0];
    const float* se_w1   = (const float*)d_in[1];
    const float* se_w2   = (const float*)d_in[2];
    const float* ch_w    = (const float*)d_in[3];
    const float* ch_b    = (const float*)d_in[4];
    const float* cw_w    = (const float*)d_in[5];
    const float* cw_b    = (const float*)d_in[6];
    const float* dh_fc1w = (const float*)d_in[7];
    const float* dh_fc1b = (const float*)d_in[8];
    const float* dh_fc2w = (const float*)d_in[9];
    const float* dh_fc2b = (const float*)d_in[10];
    const float* dw_fc1w = (const float*)d_in[11];
    const float* dw_fc1b = (const float*)d_in[12];
    const float* dw_fc2w = (const float*)d_in[13];
    const float* dw_fc2b = (const float*)d_in[14];
    float* out = (float*)d_out;

    k_mean<<<PLANES, 256>>>(x);
    k_mlp<<<B, 256>>>(se_w1, se_w2, ch_w, ch_b, cw_w, cw_b,
                      dh_fc1w, dh_fc1b, dh_fc2w, dh_fc2b,
                      dw_fc1w, dw_fc1b, dw_fc2w, dw_fc2b);
    k_apply<<<PLANES, 256>>>(x, out);
}

// round 2
// speedup vs baseline: 1.7684x; 1.7684x over previous
#include <cuda_runtime.h>
#include <math.h>

// Shapes (fixed by the problem)
#define B 32
#define C 256
#define H 64
#define W 64
#define HW (H*W)            // 4096
#define PLANES (B*C)        // 8192
#define RH 3                // int(0.05*64)
#define RW 6                // int(0.1*64)
#define CLAMP_SX 61.0f      // h - rh
#define CLAMP_SY 58.0f      // w - rw

// Scratch (no cudaMalloc allowed)
__device__ float g_mean[PLANES];
__device__ float g_scale[PLANES];
__device__ int   g_sx[PLANES];
__device__ int   g_sy[PLANES];

// ---------------------------------------------------------------------------
// Kernel 1: per-(b,c) mean of x over the 4096-element plane.
// One block per plane, 256 threads, float4 loads (fully coalesced).
// ---------------------------------------------------------------------------
__global__ void k_mean(const float* __restrict__ x) {
    int plane = blockIdx.x;
    const float4* xp = reinterpret_cast<const float4*>(x) + (size_t)plane * (HW / 4);
    int tid = threadIdx.x;

    float s = 0.f;
#pragma unroll
    for (int i = 0; i < 4; i++) {
        float4 v = xp[tid + i * 256];
        s += (v.x + v.y) + (v.z + v.w);
    }
#pragma unroll
    for (int o = 16; o; o >>= 1) s += __shfl_xor_sync(0xffffffffu, s, o);

    __shared__ float ws[8];
    if ((tid & 31) == 0) ws[tid >> 5] = s;
    __syncthreads();
    if (tid == 0) {
        float t = 0.f;
#pragma unroll
        for (int i = 0; i < 8; i++) t += ws[i];
        g_mean[plane] = t * (1.0f / (float)HW);
    }
}

// ---------------------------------------------------------------------------
// Kernel 2: MLP math, warp-per-output reductions (all weight loads coalesced).
// grid = (B, 2): blockIdx.x = batch, blockIdx.y = branch (0=h, 1=w).
// 256 threads = 8 warps.
// ---------------------------------------------------------------------------
__device__ __forceinline__ float sigmoidf_acc(float v) {
    return 1.0f / (1.0f + expf(-v));
}

__device__ __forceinline__ float warp_red(float s) {
#pragma unroll
    for (int o = 16; o; o >>= 1) s += __shfl_xor_sync(0xffffffffu, s, o);
    return s;
}

__global__ void __launch_bounds__(256) k_mlp(
    const float* __restrict__ se_w1,   // (16,256)
    const float* __restrict__ se_w2,   // (256,16)
    const float* __restrict__ ch_w, const float* __restrict__ ch_b,
    const float* __restrict__ cw_w, const float* __restrict__ cw_b,
    const float* __restrict__ dh_fc1w, const float* __restrict__ dh_fc1b,
    const float* __restrict__ dh_fc2w, const float* __restrict__ dh_fc2b,
    const float* __restrict__ dw_fc1w, const float* __restrict__ dw_fc1b,
    const float* __restrict__ dw_fc2w, const float* __restrict__ dw_fc2b)
{
    __shared__ float y[256];     // per-channel mean
    __shared__ float t1[16];     // SE hidden
    __shared__ float gv[256];    // gated mean
    __shared__ float vh[256];    // branch linear output
    __shared__ float th1[64];    // dyrelu fc1 output
    __shared__ float th2[1024];  // dyrelu fc2 output

    int b    = blockIdx.x;
    int br   = blockIdx.y;        // 0 = height branch, 1 = width branch
    int tid  = threadIdx.x;
    int wid  = tid >> 5;
    int lane = tid & 31;

    const float* cw   = br ? cw_w    : ch_w;
    const float* cb   = br ? cw_b    : ch_b;
    const float* fc1w = br ? dw_fc1w : dh_fc1w;
    const float* fc1b = br ? dw_fc1b : dh_fc1b;
    const float* fc2w = br ? dw_fc2w : dh_fc2w;
    const float* fc2b = br ? dw_fc2b : dh_fc2b;
    int* outArr = br ? g_sy : g_sx;
    float clampv = br ? CLAMP_SY : CLAMP_SX;

    y[tid] = g_mean[b * 256 + tid];
    __syncthreads();

    // Stage the per-lane slice of y once (reused across warp outputs)
    float yreg[8];
#pragma unroll
    for (int k = 0; k < 8; k++) yreg[k] = y[lane + k * 32];

    // --- SE squeeze: t1[16] = relu(y @ se_w1^T). 2 outputs per warp. ---
#pragma unroll
    for (int i = 0; i < 2; i++) {
        int o = wid * 2 + i;
        const float* r = se_w1 + o * 256;
        float s = 0.f;
#pragma unroll
        for (int k = 0; k < 8; k++) s = fmaf(yreg[k], r[lane + k * 32], s);
        s = warp_red(s);
        if (lane == 0) t1[o] = fmaxf(s, 0.f);
    }
    __syncthreads();

    // --- SE excite: scale[tid] = sigmoid(t1 . se_w2[tid,:]); gv = y*scale ---
    {
        const float4* r = reinterpret_cast<const float4*>(se_w2 + tid * 16);
        const float4* t = reinterpret_cast<const float4*>(t1);
        float s = 0.f;
#pragma unroll
        for (int j = 0; j < 4; j++) {
            float4 wv = r[j];
            float4 tv = t[j];
            s = fmaf(wv.x, tv.x, fmaf(wv.y, tv.y, fmaf(wv.z, tv.z, fmaf(wv.w, tv.w, s))));
        }
        float sg = sigmoidf_acc(s);
        if (br == 0) g_scale[b * 256 + tid] = sg;
        gv[tid] = y[tid] * sg;
    }
    __syncthreads();

    // Stage per-lane slice of gv
    float greg[8];
#pragma unroll
    for (int k = 0; k < 8; k++) greg[k] = gv[lane + k * 32];

    // --- vh[256] = gv @ cw^T + cb : 32 outputs per warp, warp-reduced ---
    for (int i = 0; i < 32; i++) {
        int o = wid * 32 + i;
        const float* r = cw + o * 256;
        float s = 0.f;
#pragma unroll
        for (int k = 0; k < 8; k++) s = fmaf(greg[k], r[lane + k * 32], s);
        s = warp_red(s);
        if (lane == 0) vh[o] = s + cb[o];
    }
    __syncthreads();

    // Stage per-lane slice of vh
    float vreg[8];
#pragma unroll
    for (int k = 0; k < 8; k++) vreg[k] = vh[lane + k * 32];

    // --- th1[64] = relu(vh @ fc1w^T + fc1b) : 8 outputs per warp ---
#pragma unroll
    for (int i = 0; i < 8; i++) {
        int o = wid * 8 + i;
        const float* r = fc1w + o * 256;
        float s = 0.f;
#pragma unroll
        for (int k = 0; k < 8; k++) s = fmaf(vreg[k], r[lane + k * 32], s);
        s = warp_red(s);
        if (lane == 0) th1[o] = fmaxf(s + fc1b[o], 0.f);
    }
    __syncthreads();

    // Stage per-lane float2 of th1 (64 inputs: lane covers [2*lane, 2*lane+1])
    float t1a = th1[lane * 2];
    float t1b = th1[lane * 2 + 1];

    // --- th2[1024] = vh-domain fc2: 128 outputs per warp, warp-reduced ---
    for (int i = 0; i < 128; i++) {
        int m = wid * 128 + i;
        float2 wv = reinterpret_cast<const float2*>(fc2w + m * 64)[lane];
        float s = fmaf(t1a, wv.x, t1b * wv.y);
        s = warp_red(s);
        if (lane == 0) th2[m] = s + fc2b[m];
    }
    __syncthreads();

    // --- per-channel dyrelu + sigmoid + ceil/clamp ---
    {
        float v = vh[tid];
        float u0 = 2.0f * sigmoidf_acc(th2[tid * 4 + 0]) - 1.0f;
        float u1 = 2.0f * sigmoidf_acc(th2[tid * 4 + 1]) - 1.0f;
        float u2 = 2.0f * sigmoidf_acc(th2[tid * 4 + 2]) - 1.0f;
        float u3 = 2.0f * sigmoidf_acc(th2[tid * 4 + 3]) - 1.0f;
        // LAMBDAS=[1,1,.5,.5], INIT_V=[1,0,0,0]
        float a0 = u0 + 1.0f;
        float a1 = u1;
        float b0 = 0.5f * u2;
        float b1 = 0.5f * u3;
        float dy = fmaxf(fmaf(v, a0, b0), fmaf(v, a1, b1));
        float sg = sigmoidf_acc(dy);
        float sv = fminf(ceilf(64.0f * sg), clampv);
        outArr[b * 256 + tid] = (int)sv;
    }
}

// ---------------------------------------------------------------------------
// Kernel 3: out = x * scale * !inside. One block per plane, float4 I/O.
// ---------------------------------------------------------------------------
__global__ void k_apply(const float* __restrict__ x, float* __restrict__ out) {
    int plane = blockIdx.x;
    float sc = g_scale[plane];
    int sx = g_sx[plane];
    int sy = g_sy[plane];

    const float4* xp = reinterpret_cast<const float4*>(x) + (size_t)plane * (HW / 4);
    float4* op = reinterpret_cast<float4*>(out) + (size_t)plane * (HW / 4);
    int tid = threadIdx.x;

#pragma unroll
    for (int i = 0; i < 4; i++) {
        int p = tid + i * 256;       // float4 index within plane
        int e = p * 4;               // element index
        int row = e >> 6;            // / 64
        int col = e & 63;            // % 64
        float4 v = xp[p];
        v.x *= sc; v.y *= sc; v.z *= sc; v.w *= sc;
        if (row >= sx && row < sx + RH) {
            if (col + 0 >= sy && col + 0 < sy + RW) v.x = 0.f;
            if (col + 1 >= sy && col + 1 < sy + RW) v.y = 0.f;
            if (col + 2 >= sy && col + 2 < sy + RW) v.z = 0.f;
            if (col + 3 >= sy && col + 3 < sy + RW) v.w = 0.f;
        }
        op[p] = v;
    }
}

// ---------------------------------------------------------------------------
extern "C" void kernel_launch(void* const* d_in, const int* in_sizes, int n_in,
                              void* d_out, int out_size) {
    const float* x       = (const float*)d_in[0];
    const float* se_w1   = (const float*)d_in[1];
    const float* se_w2   = (const float*)d_in[2];
    const float* ch_w    = (const float*)d_in[3];
    const float* ch_b    = (const float*)d_in[4];
    const float* cw_w    = (const float*)d_in[5];
    const float* cw_b    = (const float*)d_in[6];
    const float* dh_fc1w = (const float*)d_in[7];
    const float* dh_fc1b = (const float*)d_in[8];
    const float* dh_fc2w = (const float*)d_in[9];
    const float* dh_fc2b = (const float*)d_in[10];
    const float* dw_fc1w = (const float*)d_in[11];
    const float* dw_fc1b = (const float*)d_in[12];
    const float* dw_fc2w = (const float*)d_in[13];
    const float* dw_fc2b = (const float*)d_in[14];
    float* out = (float*)d_out;

    k_mean<<<PLANES, 256>>>(x);
    dim3 mg(B, 2);
    k_mlp<<<mg, 256>>>(se_w1, se_w2, ch_w, ch_b, cw_w, cw_b,
                       dh_fc1w, dh_fc1b, dh_fc2w, dh_fc2b,
                       dw_fc1w, dw_fc1b, dw_fc2w, dw_fc2b);
    k_apply<<<PLANES, 256>>>(x, out);
}

// round 3
// speedup vs baseline: 2.5440x; 1.4385x over previous
#include <cuda_runtime.h>
#include <math.h>

// Shapes (fixed by the problem)
#define B 32
#define C 256
#define H 64
#define W 64
#define HW (H*W)            // 4096
#define PLANES (B*C)        // 8192
#define RH 3                // int(0.05*64)
#define RW 6                // int(0.1*64)
#define CLAMP_SX 61.0f      // h - rh
#define CLAMP_SY 58.0f      // w - rw

// Scratch (no cudaMalloc allowed)
__device__ float g_mean[PLANES];
__device__ float g_scale[PLANES];
__device__ int   g_sx[PLANES];
__device__ int   g_sy[PLANES];

// ---------------------------------------------------------------------------
// Kernel 1: per-(b,c) mean of x over the 4096-element plane.
// One block per plane, 256 threads, float4 loads (fully coalesced).
// x stays resident in L2 (~126MB) for k_apply's second pass.
// ---------------------------------------------------------------------------
__global__ void k_mean(const float* __restrict__ x) {
    int plane = blockIdx.x;
    const float4* xp = reinterpret_cast<const float4*>(x) + (size_t)plane * (HW / 4);
    int tid = threadIdx.x;

    float s = 0.f;
#pragma unroll
    for (int i = 0; i < 4; i++) {
        float4 v = xp[tid + i * 256];
        s += (v.x + v.y) + (v.z + v.w);
    }
#pragma unroll
    for (int o = 16; o; o >>= 1) s += __shfl_xor_sync(0xffffffffu, s, o);

    __shared__ float ws[8];
    if ((tid & 31) == 0) ws[tid >> 5] = s;
    __syncthreads();
    if (tid == 0) {
        float t = 0.f;
#pragma unroll
        for (int i = 0; i < 8; i++) t += ws[i];
        g_mean[plane] = t * (1.0f / (float)HW);
    }
}

// ---------------------------------------------------------------------------
// Kernel 2: MLP math, warp-per-output reductions, 512 threads = 16 warps.
// grid = (B, 2): blockIdx.x = batch, blockIdx.y = branch (0=h, 1=w).
// ---------------------------------------------------------------------------
__device__ __forceinline__ float sigmoidf_acc(float v) {
    return 1.0f / (1.0f + expf(-v));
}

__device__ __forceinline__ float warp_red(float s) {
#pragma unroll
    for (int o = 16; o; o >>= 1) s += __shfl_xor_sync(0xffffffffu, s, o);
    return s;
}

__global__ void __launch_bounds__(512) k_mlp(
    const float* __restrict__ se_w1,   // (16,256)
    const float* __restrict__ se_w2,   // (256,16)
    const float* __restrict__ ch_w, const float* __restrict__ ch_b,
    const float* __restrict__ cw_w, const float* __restrict__ cw_b,
    const float* __restrict__ dh_fc1w, const float* __restrict__ dh_fc1b,
    const float* __restrict__ dh_fc2w, const float* __restrict__ dh_fc2b,
    const float* __restrict__ dw_fc1w, const float* __restrict__ dw_fc1b,
    const float* __restrict__ dw_fc2w, const float* __restrict__ dw_fc2b)
{
    __shared__ float y[256];     // per-channel mean
    __shared__ float t1[16];     // SE hidden
    __shared__ float gv[256];    // gated mean
    __shared__ float vh[256];    // branch linear output
    __shared__ float th1[64];    // dyrelu fc1 output
    __shared__ float th2[1024];  // dyrelu fc2 output

    int b    = blockIdx.x;
    int br   = blockIdx.y;        // 0 = height branch, 1 = width branch
    int tid  = threadIdx.x;
    int wid  = tid >> 5;          // 0..15
    int lane = tid & 31;

    const float* cw   = br ? cw_w    : ch_w;
    const float* cb   = br ? cw_b    : ch_b;
    const float* fc1w = br ? dw_fc1w : dh_fc1w;
    const float* fc1b = br ? dw_fc1b : dh_fc1b;
    const float* fc2w = br ? dw_fc2w : dh_fc2w;
    const float* fc2b = br ? dw_fc2b : dh_fc2b;
    int* outArr = br ? g_sy : g_sx;
    float clampv = br ? CLAMP_SY : CLAMP_SX;

    if (tid < 256) y[tid] = g_mean[b * 256 + tid];
    __syncthreads();

    // Stage the per-lane slice of y once (reused across warp outputs)
    float yreg[8];
#pragma unroll
    for (int k = 0; k < 8; k++) yreg[k] = y[lane + k * 32];

    // --- SE squeeze: t1[16] = relu(y @ se_w1^T). 1 output per warp. ---
    {
        const float* r = se_w1 + wid * 256;
        float s = 0.f;
#pragma unroll
        for (int k = 0; k < 8; k++) s = fmaf(yreg[k], r[lane + k * 32], s);
        s = warp_red(s);
        if (lane == 0) t1[wid] = fmaxf(s, 0.f);
    }
    __syncthreads();

    // --- SE excite: scale[c] = sigmoid(t1 . se_w2[c,:]); gv = y*scale ---
    if (tid < 256) {
        const float4* r = reinterpret_cast<const float4*>(se_w2 + tid * 16);
        const float4* t = reinterpret_cast<const float4*>(t1);
        float s = 0.f;
#pragma unroll
        for (int j = 0; j < 4; j++) {
            float4 wv = r[j];
            float4 tv = t[j];
            s = fmaf(wv.x, tv.x, fmaf(wv.y, tv.y, fmaf(wv.z, tv.z, fmaf(wv.w, tv.w, s))));
        }
        float sg = sigmoidf_acc(s);
        if (br == 0) g_scale[b * 256 + tid] = sg;
        gv[tid] = y[tid] * sg;
    }
    __syncthreads();

    // Stage per-lane slice of gv
    float greg[8];
#pragma unroll
    for (int k = 0; k < 8; k++) greg[k] = gv[lane + k * 32];

    // --- vh[256] = gv @ cw^T + cb : 16 outputs per warp, warp-reduced ---
#pragma unroll 4
    for (int i = 0; i < 16; i++) {
        int o = wid * 16 + i;
        const float* r = cw + o * 256;
        float s = 0.f;
#pragma unroll
        for (int k = 0; k < 8; k++) s = fmaf(greg[k], r[lane + k * 32], s);
        s = warp_red(s);
        if (lane == 0) vh[o] = s + cb[o];
    }
    __syncthreads();

    // Stage per-lane slice of vh
    float vreg[8];
#pragma unroll
    for (int k = 0; k < 8; k++) vreg[k] = vh[lane + k * 32];

    // --- th1[64] = relu(vh @ fc1w^T + fc1b) : 4 outputs per warp ---
#pragma unroll
    for (int i = 0; i < 4; i++) {
        int o = wid * 4 + i;
        const float* r = fc1w + o * 256;
        float s = 0.f;
#pragma unroll
        for (int k = 0; k < 8; k++) s = fmaf(vreg[k], r[lane + k * 32], s);
        s = warp_red(s);
        if (lane == 0) th1[o] = fmaxf(s + fc1b[o], 0.f);
    }
    __syncthreads();

    // Stage per-lane float2 of th1 (64 inputs: lane covers [2*lane, 2*lane+1])
    float t1a = th1[lane * 2];
    float t1b = th1[lane * 2 + 1];

    // --- th2[1024] = fc2(th1): 64 outputs per warp, warp-reduced ---
#pragma unroll 4
    for (int i = 0; i < 64; i++) {
        int m = wid * 64 + i;
        float2 wv = reinterpret_cast<const float2*>(fc2w + m * 64)[lane];
        float s = fmaf(t1a, wv.x, t1b * wv.y);
        s = warp_red(s);
        if (lane == 0) th2[m] = s + fc2b[m];
    }
    __syncthreads();

    // --- per-channel dyrelu + sigmoid + ceil/clamp ---
    if (tid < 256) {
        float v = vh[tid];
        float u0 = 2.0f * sigmoidf_acc(th2[tid * 4 + 0]) - 1.0f;
        float u1 = 2.0f * sigmoidf_acc(th2[tid * 4 + 1]) - 1.0f;
        float u2 = 2.0f * sigmoidf_acc(th2[tid * 4 + 2]) - 1.0f;
        float u3 = 2.0f * sigmoidf_acc(th2[tid * 4 + 3]) - 1.0f;
        // LAMBDAS=[1,1,.5,.5], INIT_V=[1,0,0,0]
        float a0 = u0 + 1.0f;
        float a1 = u1;
        float b0 = 0.5f * u2;
        float b1 = 0.5f * u3;
        float dy = fmaxf(fmaf(v, a0, b0), fmaf(v, a1, b1));
        float sg = sigmoidf_acc(dy);
        float sv = fminf(ceilf(64.0f * sg), clampv);
        outArr[b * 256 + tid] = (int)sv;
    }
}

// ---------------------------------------------------------------------------
// Kernel 3: out = x * scale * !inside. One block per plane, float4 I/O.
// REVERSE plane order: x (~128MB) nearly fits L2 (~126MB); the tail of
// k_mean's reads is freshest, so reading tail-first maximizes L2 hits.
// Output stores use __stcs (streaming) to avoid evicting x from L2.
// ---------------------------------------------------------------------------
__global__ void k_apply(const float* __restrict__ x, float* __restrict__ out) {
    int plane = (PLANES - 1) - blockIdx.x;
    float sc = g_scale[plane];
    int sx = g_sx[plane];
    int sy = g_sy[plane];

    const float4* xp = reinterpret_cast<const float4*>(x) + (size_t)plane * (HW / 4);
    float4* op = reinterpret_cast<float4*>(out) + (size_t)plane * (HW / 4);
    int tid = threadIdx.x;

#pragma unroll
    for (int i = 0; i < 4; i++) {
        int p = tid + i * 256;       // float4 index within plane
        int e = p * 4;               // element index
        int row = e >> 6;            // / 64
        int col = e & 63;            // % 64
        float4 v = xp[p];
        v.x *= sc; v.y *= sc; v.z *= sc; v.w *= sc;
        if (row >= sx && row < sx + RH) {
            if (col + 0 >= sy && col + 0 < sy + RW) v.x = 0.f;
            if (col + 1 >= sy && col + 1 < sy + RW) v.y = 0.f;
            if (col + 2 >= sy && col + 2 < sy + RW) v.z = 0.f;
            if (col + 3 >= sy && col + 3 < sy + RW) v.w = 0.f;
        }
        __stcs(op + p, v);
    }
}

// ---------------------------------------------------------------------------
extern "C" void kernel_launch(void* const* d_in, const int* in_sizes, int n_in,
                              void* d_out, int out_size) {
    const float* x       = (const float*)d_in[0];
    const float* se_w1   = (const float*)d_in[1];
    const float* se_w2   = (const float*)d_in[2];
    const float* ch_w    = (const float*)d_in[3];
    const float* ch_b    = (const float*)d_in[4];
    const float* cw_w    = (const float*)d_in[5];
    const float* cw_b    = (const float*)d_in[6];
    const float* dh_fc1w = (const float*)d_in[7];
    const float* dh_fc1b = (const float*)d_in[8];
    const float* dh_fc2w = (const float*)d_in[9];
    const float* dh_fc2b = (const float*)d_in[10];
    const float* dw_fc1w = (const float*)d_in[11];
    const float* dw_fc1b = (const float*)d_in[12];
    const float* dw_fc2w = (const float*)d_in[13];
    const float* dw_fc2b = (const float*)d_in[14];
    float* out = (float*)d_out;

    k_mean<<<PLANES, 256>>>(x);
    dim3 mg(B, 2);
    k_mlp<<<mg, 512>>>(se_w1, se_w2, ch_w, ch_b, cw_w, cw_b,
                       dh_fc1w, dh_fc1b, dh_fc2w, dh_fc2b,
                       dw_fc1w, dw_fc1b, dw_fc2w, dw_fc2b);
    k_apply<<<PLANES, 256>>>(x, out);
}